// round 1
// baseline (speedup 1.0000x reference)
#include <cuda_runtime.h>
#include <math.h>

// ---------------------------------------------------------------------------
// CMAF fused block, fp32 baseline.
// Pipeline:
//   K1 k_proj_spatial : P0 = LN(x_spatial @ Ws^T + b) + mod        [GEMM K=1280, LN epi]
//   K2 k_proj_gf      : P1,P2 = LN(x_{g,f} @ Wgf^T + b) + mod      [GEMM K=128,  LN epi]
//   K3 k_qkv          : 15 jobs (q / k,s / v,s per stream)         [GEMM K=128, bias epi]
//   K4 k_attn         : per-(b,n) 4-head softmax over 2 keys       [warp kernel]
//   K5 k_outproj      : x1 = LN(o @ Wo^T + b + P)                  [GEMM K=128, resid+LN epi]
//   K6 k_ffn1         : h = gelu(x1 @ W1^T + b)                    [GEMM K=128, gelu epi]
//   K7 k_ffn2         : x2 = LN(h @ W2^T + b + x1)                 [GEMM K=256, resid+LN epi]
//   K8 k_gate         : gates = softmax(flat @ Gw^T + Gb); fuse    [warp kernel]
// ---------------------------------------------------------------------------

#define MAXB 65536

// Scratch (static __device__ — no allocations anywhere).
__device__ __align__(16) float g_P [MAXB * 3 * 128];
__device__ __align__(16) float g_q [MAXB * 3 * 128];
__device__ __align__(16) float g_k [MAXB * 3 * 2 * 128];
__device__ __align__(16) float g_v [MAXB * 3 * 2 * 128];
__device__ __align__(16) float g_o [MAXB * 3 * 128];
__device__ __align__(16) float g_x1[MAXB * 3 * 128];
__device__ __align__(16) float g_h [MAXB * 3 * 256];
__device__ __align__(16) float g_x2[MAXB * 3 * 128];

__constant__ int c_kv[3][2] = {{1, 2}, {0, 2}, {0, 1}};

__device__ __forceinline__ float wsum(float v) {
#pragma unroll
    for (int o = 16; o; o >>= 1) v += __shfl_xor_sync(0xffffffffu, v, o);
    return v;
}

// ---------------------------------------------------------------------------
// Tiled GEMM core: C_tile[64 x 128] += A[m0:m0+64, :K] * W[0:128, :K]^T
// A row-major (stride lda), W row-major (stride K). 256 threads.
// Thread (g = tid>>5, c = tid&31) owns rows m0+g*8..+7, cols c*4..c*4+3.
// Double-buffered smem with register prefetch (single __syncthreads per tile).
// ---------------------------------------------------------------------------
__device__ __forceinline__ void gemm_core(
    const float* __restrict__ A, int lda, int m0, int M,
    const float* __restrict__ W, int K,
    float acc[8][4])
{
    __shared__ float As[2][64][20];   // [buf][m][k] (pad 16->20, keeps f4 stores aligned)
    __shared__ float Ws[2][16][128];  // [buf][k][n] transposed for vector b-frag loads

    const int tid  = threadIdx.x;
    const int g    = tid >> 5;
    const int c    = tid & 31;
    const int aRow = tid >> 2;            // 0..63
    const int aK   = (tid & 3) * 4;       // 0,4,8,12
    const int wRow = tid >> 1;            // 0..127
    const int wK   = (tid & 1) * 8;       // 0,8

    const int arow_g = min(m0 + aRow, M - 1);
    const float* Aptr = A + (long)arow_g * lda;
    const float* Wptr = W + (long)wRow * K;

    const int ntiles = K / 16;

    float4 ra  = *(const float4*)(Aptr + aK);
    float4 rw0 = *(const float4*)(Wptr + wK);
    float4 rw1 = *(const float4*)(Wptr + wK + 4);

    *(float4*)(&As[0][aRow][aK]) = ra;
    Ws[0][wK + 0][wRow] = rw0.x; Ws[0][wK + 1][wRow] = rw0.y;
    Ws[0][wK + 2][wRow] = rw0.z; Ws[0][wK + 3][wRow] = rw0.w;
    Ws[0][wK + 4][wRow] = rw1.x; Ws[0][wK + 5][wRow] = rw1.y;
    Ws[0][wK + 6][wRow] = rw1.z; Ws[0][wK + 7][wRow] = rw1.w;
    __syncthreads();

    for (int t = 0; t < ntiles; ++t) {
        const int cur = t & 1, nxt = cur ^ 1;
        if (t + 1 < ntiles) {
            const int k0 = (t + 1) * 16;
            ra  = *(const float4*)(Aptr + k0 + aK);
            rw0 = *(const float4*)(Wptr + k0 + wK);
            rw1 = *(const float4*)(Wptr + k0 + wK + 4);
        }
#pragma unroll
        for (int kk = 0; kk < 16; ++kk) {
            const float4 b4 = *(const float4*)(&Ws[cur][kk][c * 4]);
#pragma unroll
            for (int i = 0; i < 8; ++i) {
                const float a = As[cur][g * 8 + i][kk];
                acc[i][0] += a * b4.x;
                acc[i][1] += a * b4.y;
                acc[i][2] += a * b4.z;
                acc[i][3] += a * b4.w;
            }
        }
        if (t + 1 < ntiles) {
            *(float4*)(&As[nxt][aRow][aK]) = ra;
            Ws[nxt][wK + 0][wRow] = rw0.x; Ws[nxt][wK + 1][wRow] = rw0.y;
            Ws[nxt][wK + 2][wRow] = rw0.z; Ws[nxt][wK + 3][wRow] = rw0.w;
            Ws[nxt][wK + 4][wRow] = rw1.x; Ws[nxt][wK + 5][wRow] = rw1.y;
            Ws[nxt][wK + 6][wRow] = rw1.z; Ws[nxt][wK + 7][wRow] = rw1.w;
        }
        __syncthreads();
    }
}

// ---------------- Epilogues ----------------

// bias + (optional residual) + LayerNorm + (optional additive vec) -> out
__device__ __forceinline__ void epi_ln(
    float acc[8][4], int m0, int M,
    const float* __restrict__ bias,
    const float* __restrict__ resid, int rstride,
    const float* __restrict__ lng, const float* __restrict__ lnb,
    const float* __restrict__ addv,
    float* __restrict__ outp, int ostride)
{
    const int g = threadIdx.x >> 5, c = threadIdx.x & 31;
    const int col = c * 4;
    float bb[4], gg[4], lb[4], mv[4];
#pragma unroll
    for (int j = 0; j < 4; ++j) {
        bb[j] = bias[col + j];
        gg[j] = lng[col + j];
        lb[j] = lnb[col + j];
        mv[j] = addv ? addv[col + j] : 0.f;
    }
#pragma unroll
    for (int i = 0; i < 8; ++i) {
        const int m = m0 + g * 8 + i;
        if (m >= M) return;  // uniform across warp (all lanes share g,i)
        float v[4];
#pragma unroll
        for (int j = 0; j < 4; ++j) v[j] = acc[i][j] + bb[j];
        if (resid) {
            const float* rr = resid + (long)m * rstride + col;
#pragma unroll
            for (int j = 0; j < 4; ++j) v[j] += rr[j];
        }
        float s  = v[0] + v[1] + v[2] + v[3];
        float s2 = v[0] * v[0] + v[1] * v[1] + v[2] * v[2] + v[3] * v[3];
        s  = wsum(s);
        s2 = wsum(s2);
        const float mean = s * 0.0078125f;                 // /128
        const float var  = s2 * 0.0078125f - mean * mean;
        const float rs   = rsqrtf(var + 1e-5f);
        float* orow = outp + (long)m * ostride + col;
#pragma unroll
        for (int j = 0; j < 4; ++j)
            orow[j] = (v[j] - mean) * rs * gg[j] + lb[j] + mv[j];
    }
}

__device__ __forceinline__ void epi_bias(
    float acc[8][4], int m0, int M,
    const float* __restrict__ bias,
    float* __restrict__ outp, int ostride)
{
    const int g = threadIdx.x >> 5, c = threadIdx.x & 31;
    const int col = c * 4;
    float bb[4];
#pragma unroll
    for (int j = 0; j < 4; ++j) bb[j] = bias[col + j];
#pragma unroll
    for (int i = 0; i < 8; ++i) {
        const int m = m0 + g * 8 + i;
        if (m >= M) return;
        float* orow = outp + (long)m * ostride + col;
#pragma unroll
        for (int j = 0; j < 4; ++j) orow[j] = acc[i][j] + bb[j];
    }
}

__device__ __forceinline__ void epi_gelu(
    float acc[8][4], int m0, int M,
    const float* __restrict__ bias,
    float* __restrict__ outp, int ostride)
{
    const int g = threadIdx.x >> 5, c = threadIdx.x & 31;
    const int col = c * 4;
    float bb[4];
#pragma unroll
    for (int j = 0; j < 4; ++j) bb[j] = bias[col + j];
#pragma unroll
    for (int i = 0; i < 8; ++i) {
        const int m = m0 + g * 8 + i;
        if (m >= M) return;
        float* orow = outp + (long)m * ostride + col;
#pragma unroll
        for (int j = 0; j < 4; ++j) {
            const float x = acc[i][j] + bb[j];
            orow[j] = x * 0.5f * (1.0f + erff(x * 0.70710678118654752f));  // exact gelu
        }
    }
}

// ---------------- Kernels ----------------

__global__ __launch_bounds__(256) void k_proj_spatial(
    const float* __restrict__ X, const float* __restrict__ W,
    const float* __restrict__ pb, const float* __restrict__ lng,
    const float* __restrict__ lnb, const float* __restrict__ mod, int M)
{
    float acc[8][4] = {};
    const int m0 = blockIdx.x * 64;
    gemm_core(X, 1280, m0, M, W, 1280, acc);
    epi_ln(acc, m0, M, pb, nullptr, 0, lng, lnb, mod, g_P, 384);
}

__global__ __launch_bounds__(256) void k_proj_gf(
    const float* __restrict__ Xg, const float* __restrict__ Xf,
    const float* __restrict__ Wgf,
    const float* __restrict__ pb, const float* __restrict__ lng,
    const float* __restrict__ lnb, const float* __restrict__ mod, int M)
{
    const int s = blockIdx.y;      // 0 -> gradient(stream1), 1 -> frequency(stream2)
    const int n = s + 1;
    const float* A = s ? Xf : Xg;
    const float* W = Wgf + s * 128 * 128;
    float acc[8][4] = {};
    const int m0 = blockIdx.x * 64;
    gemm_core(A, 128, m0, M, W, 128, acc);
    epi_ln(acc, m0, M, pb + n * 128, nullptr, 0,
           lng + n * 128, lnb + n * 128, mod + n * 128, g_P + n * 128, 384);
}

__global__ __launch_bounds__(256) void k_qkv(
    const float* __restrict__ Wi, const float* __restrict__ Bi, int M)
{
    const int j = blockIdx.y;   // 0..14
    const int n = j / 5, t = j % 5;
    int src, wpart, outoff, ostride;
    float* outbuf;
    if (t == 0)      { src = n;              wpart = 0; outbuf = g_q; outoff = n * 128;             ostride = 384; }
    else if (t <= 2) { const int s = t - 1;  src = c_kv[n][s]; wpart = 1; outbuf = g_k; outoff = (n * 2 + s) * 128; ostride = 768; }
    else             { const int s = t - 3;  src = c_kv[n][s]; wpart = 2; outbuf = g_v; outoff = (n * 2 + s) * 128; ostride = 768; }
    const float* A    = g_P + src * 128;
    const float* W    = Wi + n * 384 * 128 + wpart * 128 * 128;
    const float* bias = Bi + n * 384 + wpart * 128;
    float acc[8][4] = {};
    const int m0 = blockIdx.x * 64;
    gemm_core(A, 384, m0, M, W, 128, acc);
    epi_bias(acc, m0, M, bias, outbuf + outoff, ostride);
}

__global__ __launch_bounds__(256) void k_attn(int M)
{
    const int rid = blockIdx.x * 8 + (threadIdx.x >> 5);
    if (rid >= M * 3) return;
    const int lane = threadIdx.x & 31;
    const int b = rid / 3, n = rid % 3;
    const float* qr = g_q + ((long)b * 3 + n) * 128;
    const float* kr = g_k + ((long)b * 3 + n) * 2 * 128;
    const float* vr = g_v + ((long)b * 3 + n) * 2 * 128;
    float* orow     = g_o + ((long)b * 3 + n) * 128;
    const float scale = 0.17677669529663687f;  // 1/sqrt(32)
#pragma unroll
    for (int h = 0; h < 4; ++h) {
        const int d = h * 32 + lane;
        const float qv = qr[d];
        float s0 = qv * kr[d];
        float s1 = qv * kr[128 + d];
        s0 = wsum(s0) * scale;
        s1 = wsum(s1) * scale;
        const float mx = fmaxf(s0, s1);
        const float e0 = expf(s0 - mx), e1 = expf(s1 - mx);
        const float inv = 1.0f / (e0 + e1);
        orow[d] = (e0 * inv) * vr[d] + (e1 * inv) * vr[128 + d];
    }
}

__global__ __launch_bounds__(256) void k_outproj(
    const float* __restrict__ Wo, const float* __restrict__ bo,
    const float* __restrict__ ag, const float* __restrict__ ab, int M)
{
    const int n = blockIdx.y;
    float acc[8][4] = {};
    const int m0 = blockIdx.x * 64;
    gemm_core(g_o + n * 128, 384, m0, M, Wo + n * 128 * 128, 128, acc);
    epi_ln(acc, m0, M, bo + n * 128, g_P + n * 128, 384,
           ag + n * 128, ab + n * 128, nullptr, g_x1 + n * 128, 384);
}

__global__ __launch_bounds__(256) void k_ffn1(
    const float* __restrict__ W1, const float* __restrict__ B1, int M)
{
    const int j = blockIdx.y;        // 0..5
    const int n = j >> 1, tl = j & 1;
    float acc[8][4] = {};
    const int m0 = blockIdx.x * 64;
    gemm_core(g_x1 + n * 128, 384, m0, M,
              W1 + n * 256 * 128 + tl * 128 * 128, 128, acc);
    epi_gelu(acc, m0, M, B1 + n * 256 + tl * 128, g_h + n * 256 + tl * 128, 768);
}

__global__ __launch_bounds__(256) void k_ffn2(
    const float* __restrict__ W2, const float* __restrict__ B2,
    const float* __restrict__ fg, const float* __restrict__ fb, int M)
{
    const int n = blockIdx.y;
    float acc[8][4] = {};
    const int m0 = blockIdx.x * 64;
    gemm_core(g_h + n * 256, 768, m0, M, W2 + n * 128 * 256, 256, acc);
    epi_ln(acc, m0, M, B2 + n * 128, g_x1 + n * 128, 384,
           fg + n * 128, fb + n * 128, nullptr, g_x2 + n * 128, 384);
}

__global__ __launch_bounds__(256) void k_gate(
    const float* __restrict__ gw, const float* __restrict__ gb,
    float* __restrict__ out, int M)
{
    const int b = blockIdx.x * 8 + (threadIdx.x >> 5);
    if (b >= M) return;
    const int lane = threadIdx.x & 31;
    const float* xr = g_x2 + (long)b * 384;
    float l0 = 0.f, l1 = 0.f, l2 = 0.f;
#pragma unroll
    for (int j = 0; j < 12; ++j) {
        const int idx = lane + 32 * j;
        const float x = xr[idx];
        l0 += x * gw[idx];
        l1 += x * gw[384 + idx];
        l2 += x * gw[768 + idx];
    }
    l0 = wsum(l0) + gb[0];
    l1 = wsum(l1) + gb[1];
    l2 = wsum(l2) + gb[2];
    const float mx = fmaxf(l0, fmaxf(l1, l2));
    const float e0 = expf(l0 - mx), e1 = expf(l1 - mx), e2 = expf(l2 - mx);
    const float inv = 1.0f / (e0 + e1 + e2);
    const float w0 = e0 * inv, w1 = e1 * inv, w2 = e2 * inv;
#pragma unroll
    for (int j = 0; j < 4; ++j) {
        const int d = lane + 32 * j;
        out[(long)b * 128 + d] = w0 * xr[d] + w1 * xr[128 + d] + w2 * xr[256 + d];
    }
}

// ---------------------------------------------------------------------------

extern "C" void kernel_launch(void* const* d_in, const int* in_sizes, int n_in,
                              void* d_out, int out_size)
{
    const float* x_spatial   = (const float*)d_in[0];
    const float* x_gradient  = (const float*)d_in[1];
    const float* x_frequency = (const float*)d_in[2];
    const float* w_spatial   = (const float*)d_in[3];
    const float* w_gf        = (const float*)d_in[4];
    const float* proj_b      = (const float*)d_in[5];
    const float* proj_ln_g   = (const float*)d_in[6];
    const float* proj_ln_b   = (const float*)d_in[7];
    const float* mod_emb     = (const float*)d_in[8];
    const float* in_w        = (const float*)d_in[9];
    const float* in_b        = (const float*)d_in[10];
    const float* out_w       = (const float*)d_in[11];
    const float* out_b       = (const float*)d_in[12];
    const float* attn_g      = (const float*)d_in[13];
    const float* attn_b      = (const float*)d_in[14];
    const float* w1          = (const float*)d_in[15];
    const float* b1          = (const float*)d_in[16];
    const float* w2          = (const float*)d_in[17];
    const float* b2          = (const float*)d_in[18];
    const float* ffn_g       = (const float*)d_in[19];
    const float* ffn_b       = (const float*)d_in[20];
    const float* gate_w      = (const float*)d_in[21];
    const float* gate_b      = (const float*)d_in[22];
    float* out = (float*)d_out;

    int B = in_sizes[0] / 1280;
    if (B > MAXB) B = MAXB;
    const int gm = (B + 63) / 64;

    k_proj_spatial<<<dim3(gm, 1), 256>>>(x_spatial, w_spatial, proj_b,
                                         proj_ln_g, proj_ln_b, mod_emb, B);
    k_proj_gf<<<dim3(gm, 2), 256>>>(x_gradient, x_frequency, w_gf, proj_b,
                                    proj_ln_g, proj_ln_b, mod_emb, B);
    k_qkv<<<dim3(gm, 15), 256>>>(in_w, in_b, B);
    k_attn<<<(B * 3 + 7) / 8, 256>>>(B);
    k_outproj<<<dim3(gm, 3), 256>>>(out_w, out_b, attn_g, attn_b, B);
    k_ffn1<<<dim3(gm, 6), 256>>>(w1, b1, B);
    k_ffn2<<<dim3(gm, 3), 256>>>(w2, b2, ffn_g, ffn_b, B);
    k_gate<<<(B + 7) / 8, 256>>>(gate_w, gate_b, out, B);
}

// round 2
// speedup vs baseline: 1.5063x; 1.5063x over previous
#include <cuda_runtime.h>
#include <math.h>

// ---------------------------------------------------------------------------
// CMAF fused block, round 2: all GEMMs on tensor pipe (mma.sync tf32).
//   gemm: C[M,128] = A[M,K] @ W[128,K]^T   (BM=128, BN=128, BK=16, 256 thr)
//   LN stages as separate warp-per-row kernels (memory-bound, ~25us each).
// ---------------------------------------------------------------------------

#define MAXB 65536

__device__ __align__(16) float g_P [MAXB * 3 * 128];
__device__ __align__(16) float g_q [MAXB * 3 * 128];
__device__ __align__(16) float g_k [MAXB * 6 * 128];
__device__ __align__(16) float g_v [MAXB * 6 * 128];
__device__ __align__(16) float g_o [MAXB * 3 * 128];
__device__ __align__(16) float g_x1[MAXB * 3 * 128];
__device__ __align__(16) float g_h [MAXB * 3 * 256];
__device__ __align__(16) float g_x2[MAXB * 3 * 128];

__constant__ int c_kv[3][2] = {{1, 2}, {0, 2}, {0, 1}};

__device__ __forceinline__ float wsum(float v) {
#pragma unroll
    for (int o = 16; o; o >>= 1) v += __shfl_xor_sync(0xffffffffu, v, o);
    return v;
}

__device__ __forceinline__ unsigned f2tf(float f) {
    unsigned u;
    asm("cvt.rna.tf32.f32 %0, %1;" : "=r"(u) : "f"(f));
    return u;
}

__device__ __forceinline__ void mma8(float c[4], const unsigned a[4], const unsigned b[2]) {
    asm volatile(
        "mma.sync.aligned.m16n8k8.row.col.f32.tf32.tf32.f32 "
        "{%0,%1,%2,%3}, {%4,%5,%6,%7}, {%8,%9}, {%0,%1,%2,%3};\n"
        : "+f"(c[0]), "+f"(c[1]), "+f"(c[2]), "+f"(c[3])
        : "r"(a[0]), "r"(a[1]), "r"(a[2]), "r"(a[3]), "r"(b[0]), "r"(b[1]));
}

// ---------------------------------------------------------------------------
// Tensor-core GEMM core. EPI: 0 = bias, 1 = bias+gelu(exact).
// Thread block 256 = 8 warps; warp (wid&3 -> m 32-slab, wid>>2 -> n 64-slab).
// mma m16n8k8 tf32: per warp 2 m-tiles x 8 n-tiles.
// ---------------------------------------------------------------------------
template <int EPI>
__device__ __forceinline__ void mma_gemm(
    const float* __restrict__ A, int lda,
    const float* __restrict__ W, int K,
    const float* __restrict__ bias,
    float* __restrict__ out, int ostride,
    int m0, int M)
{
    __shared__ unsigned As[2][128][17];
    __shared__ unsigned Ws[2][128][17];

    const int tid   = threadIdx.x;
    const int ldRow = tid >> 1;          // 0..127
    const int ldCol = (tid & 1) * 8;     // 0 or 8

    const float* Aptr = A + (long)min(m0 + ldRow, M - 1) * lda + ldCol;
    const float* Wptr = W + (long)ldRow * K + ldCol;

    const int wid = tid >> 5, lane = tid & 31;
    const int wm = (wid & 3) * 32;
    const int wn = (wid >> 2) * 64;
    const int g  = lane >> 2, t4 = lane & 3;

    float acc[2][8][4] = {};

    const int ntiles = K >> 4;

    float4 ra0 = *(const float4*)(Aptr);
    float4 ra1 = *(const float4*)(Aptr + 4);
    float4 rw0 = *(const float4*)(Wptr);
    float4 rw1 = *(const float4*)(Wptr + 4);

    {
        unsigned* as = &As[0][ldRow][ldCol];
        as[0] = f2tf(ra0.x); as[1] = f2tf(ra0.y); as[2] = f2tf(ra0.z); as[3] = f2tf(ra0.w);
        as[4] = f2tf(ra1.x); as[5] = f2tf(ra1.y); as[6] = f2tf(ra1.z); as[7] = f2tf(ra1.w);
        unsigned* ws = &Ws[0][ldRow][ldCol];
        ws[0] = f2tf(rw0.x); ws[1] = f2tf(rw0.y); ws[2] = f2tf(rw0.z); ws[3] = f2tf(rw0.w);
        ws[4] = f2tf(rw1.x); ws[5] = f2tf(rw1.y); ws[6] = f2tf(rw1.z); ws[7] = f2tf(rw1.w);
    }
    __syncthreads();

    for (int t = 0; t < ntiles; ++t) {
        const int cur = t & 1, nxt = cur ^ 1;
        if (t + 1 < ntiles) {
            const int k0 = (t + 1) << 4;
            ra0 = *(const float4*)(Aptr + k0);
            ra1 = *(const float4*)(Aptr + k0 + 4);
            rw0 = *(const float4*)(Wptr + k0);
            rw1 = *(const float4*)(Wptr + k0 + 4);
        }
#pragma unroll
        for (int ks = 0; ks < 16; ks += 8) {
            unsigned af[2][4];
#pragma unroll
            for (int mt = 0; mt < 2; ++mt) {
                const int r = wm + mt * 16 + g;
                af[mt][0] = As[cur][r][ks + t4];
                af[mt][1] = As[cur][r + 8][ks + t4];
                af[mt][2] = As[cur][r][ks + t4 + 4];
                af[mt][3] = As[cur][r + 8][ks + t4 + 4];
            }
            unsigned bf[8][2];
#pragma unroll
            for (int nt = 0; nt < 8; ++nt) {
                const int n = wn + nt * 8 + g;
                bf[nt][0] = Ws[cur][n][ks + t4];
                bf[nt][1] = Ws[cur][n][ks + t4 + 4];
            }
#pragma unroll
            for (int mt = 0; mt < 2; ++mt)
#pragma unroll
                for (int nt = 0; nt < 8; ++nt)
                    mma8(acc[mt][nt], af[mt], bf[nt]);
        }
        if (t + 1 < ntiles) {
            unsigned* as = &As[nxt][ldRow][ldCol];
            as[0] = f2tf(ra0.x); as[1] = f2tf(ra0.y); as[2] = f2tf(ra0.z); as[3] = f2tf(ra0.w);
            as[4] = f2tf(ra1.x); as[5] = f2tf(ra1.y); as[6] = f2tf(ra1.z); as[7] = f2tf(ra1.w);
            unsigned* ws = &Ws[nxt][ldRow][ldCol];
            ws[0] = f2tf(rw0.x); ws[1] = f2tf(rw0.y); ws[2] = f2tf(rw0.z); ws[3] = f2tf(rw0.w);
            ws[4] = f2tf(rw1.x); ws[5] = f2tf(rw1.y); ws[6] = f2tf(rw1.z); ws[7] = f2tf(rw1.w);
        }
        __syncthreads();
    }

    // ---- epilogue: bias (+gelu) ----
    float bcol[8][2];
#pragma unroll
    for (int nt = 0; nt < 8; ++nt) {
        const int col = wn + nt * 8 + t4 * 2;
        bcol[nt][0] = bias[col];
        bcol[nt][1] = bias[col + 1];
    }
#pragma unroll
    for (int mt = 0; mt < 2; ++mt)
#pragma unroll
        for (int half = 0; half < 2; ++half) {
            const int r = m0 + wm + mt * 16 + half * 8 + g;
            if (r < M) {
                float* orow = out + (long)r * ostride;
#pragma unroll
                for (int nt = 0; nt < 8; ++nt) {
                    const int col = wn + nt * 8 + t4 * 2;
                    float c0 = acc[mt][nt][half * 2 + 0] + bcol[nt][0];
                    float c1 = acc[mt][nt][half * 2 + 1] + bcol[nt][1];
                    if (EPI == 1) {
                        c0 = c0 * 0.5f * (1.0f + erff(c0 * 0.70710678118654752f));
                        c1 = c1 * 0.5f * (1.0f + erff(c1 * 0.70710678118654752f));
                    }
                    *(float2*)(orow + col) = make_float2(c0, c1);
                }
            }
        }
}

// ---------------- GEMM wrappers ----------------

__global__ __launch_bounds__(256) void k_g_spatial(
    const float* __restrict__ X, const float* __restrict__ W,
    const float* __restrict__ pb, int M)
{
    mma_gemm<0>(X, 1280, W, 1280, pb, g_P, 384, blockIdx.x * 128, M);
}

__global__ __launch_bounds__(256) void k_g_gf(
    const float* __restrict__ Xg, const float* __restrict__ Xf,
    const float* __restrict__ Wgf, const float* __restrict__ pb, int M)
{
    const int s = blockIdx.y;     // 0->grad(n=1), 1->freq(n=2)
    const int n = s + 1;
    mma_gemm<0>(s ? Xf : Xg, 128, Wgf + s * 128 * 128, 128,
                pb + n * 128, g_P + n * 128, 384, blockIdx.x * 128, M);
}

__global__ __launch_bounds__(256) void k_g_qkv(
    const float* __restrict__ Wi, const float* __restrict__ Bi, int M)
{
    const int j = blockIdx.y;   // 0..14
    const int n = j / 5, t = j % 5;
    int src, wpart, outoff, ostride;
    float* outbuf;
    if (t == 0)      { src = n;             wpart = 0; outbuf = g_q; outoff = n * 128;               ostride = 384; }
    else if (t <= 2) { const int s = t - 1; src = c_kv[n][s]; wpart = 1; outbuf = g_k; outoff = (n * 2 + s) * 128; ostride = 768; }
    else             { const int s = t - 3; src = c_kv[n][s]; wpart = 2; outbuf = g_v; outoff = (n * 2 + s) * 128; ostride = 768; }
    mma_gemm<0>(g_P + src * 128, 384,
                Wi + n * 384 * 128 + wpart * 128 * 128, 128,
                Bi + n * 384 + wpart * 128,
                outbuf + outoff, ostride, blockIdx.x * 128, M);
}

__global__ __launch_bounds__(256) void k_g_outproj(
    const float* __restrict__ Wo, const float* __restrict__ bo, int M)
{
    const int n = blockIdx.y;
    mma_gemm<0>(g_o + n * 128, 384, Wo + n * 128 * 128, 128,
                bo + n * 128, g_x1 + n * 128, 384, blockIdx.x * 128, M);
}

__global__ __launch_bounds__(256) void k_g_ffn1(
    const float* __restrict__ W1, const float* __restrict__ B1, int M)
{
    const int j = blockIdx.y;    // 0..5
    const int n = j >> 1, tl = j & 1;
    mma_gemm<1>(g_x1 + n * 128, 384,
                W1 + n * 256 * 128 + tl * 128 * 128, 128,
                B1 + n * 256 + tl * 128,
                g_h + n * 256 + tl * 128, 768, blockIdx.x * 128, M);
}

__global__ __launch_bounds__(256) void k_g_ffn2(
    const float* __restrict__ W2, const float* __restrict__ B2, int M)
{
    const int n = blockIdx.y;
    mma_gemm<0>(g_h + n * 256, 768, W2 + n * 128 * 256, 256,
                B2 + n * 128, g_x2 + n * 128, 384, blockIdx.x * 128, M);
}

// ---------------- LayerNorm passes ----------------
// mode 0: g_P  = LN(g_P)*g+b + mod      (proj)
// mode 1: g_x1 = LN(g_x1 + g_P)*g+b     (post-attn)
// mode 2: g_x2 = LN(g_x2 + g_x1)*g+b    (post-ffn)
__global__ __launch_bounds__(256) void k_ln(
    int mode,
    const float* __restrict__ gamma, const float* __restrict__ beta,
    const float* __restrict__ addv, int R)
{
    const int row = blockIdx.x * 8 + (threadIdx.x >> 5);
    if (row >= R) return;
    const int lane = threadIdx.x & 31;
    const int n = row % 3;

    float* io = (mode == 0) ? g_P : (mode == 1 ? g_x1 : g_x2);
    const float* resid = (mode == 0) ? nullptr : (mode == 1 ? g_P : g_x1);

    const long off = (long)row * 128 + lane * 4;
    float4 v = *(const float4*)(io + off);
    if (resid) {
        float4 r4 = *(const float4*)(resid + off);
        v.x += r4.x; v.y += r4.y; v.z += r4.z; v.w += r4.w;
    }
    float s  = v.x + v.y + v.z + v.w;
    float s2 = v.x * v.x + v.y * v.y + v.z * v.z + v.w * v.w;
    s  = wsum(s);
    s2 = wsum(s2);
    const float mean = s * 0.0078125f;
    const float var  = s2 * 0.0078125f - mean * mean;
    const float rs   = rsqrtf(var + 1e-5f);

    const int pidx = n * 128 + lane * 4;
    const float4 g4 = *(const float4*)(gamma + pidx);
    const float4 b4 = *(const float4*)(beta + pidx);
    float4 m4 = make_float4(0.f, 0.f, 0.f, 0.f);
    if (addv) m4 = *(const float4*)(addv + pidx);

    float4 o;
    o.x = (v.x - mean) * rs * g4.x + b4.x + m4.x;
    o.y = (v.y - mean) * rs * g4.y + b4.y + m4.y;
    o.z = (v.z - mean) * rs * g4.z + b4.z + m4.z;
    o.w = (v.w - mean) * rs * g4.w + b4.w + m4.w;
    *(float4*)(io + off) = o;
}

// ---------------- Attention + gate (unchanged) ----------------

__global__ __launch_bounds__(256) void k_attn(int M)
{
    const int rid = blockIdx.x * 8 + (threadIdx.x >> 5);
    if (rid >= M * 3) return;
    const int lane = threadIdx.x & 31;
    const long base = (long)rid * 128;
    const float* qr = g_q + base;
    const float* kr = g_k + base * 2;
    const float* vr = g_v + base * 2;
    float* orow     = g_o + base;
    const float scale = 0.17677669529663687f;  // 1/sqrt(32)
#pragma unroll
    for (int h = 0; h < 4; ++h) {
        const int d = h * 32 + lane;
        const float qv = qr[d];
        float s0 = qv * kr[d];
        float s1 = qv * kr[128 + d];
        s0 = wsum(s0) * scale;
        s1 = wsum(s1) * scale;
        const float mx = fmaxf(s0, s1);
        const float e0 = expf(s0 - mx), e1 = expf(s1 - mx);
        const float inv = 1.0f / (e0 + e1);
        orow[d] = (e0 * inv) * vr[d] + (e1 * inv) * vr[128 + d];
    }
}

__global__ __launch_bounds__(256) void k_gate(
    const float* __restrict__ gw, const float* __restrict__ gb,
    float* __restrict__ out, int M)
{
    const int b = blockIdx.x * 8 + (threadIdx.x >> 5);
    if (b >= M) return;
    const int lane = threadIdx.x & 31;
    const float* xr = g_x2 + (long)b * 384;
    float l0 = 0.f, l1 = 0.f, l2 = 0.f;
#pragma unroll
    for (int j = 0; j < 12; ++j) {
        const int idx = lane + 32 * j;
        const float x = xr[idx];
        l0 += x * gw[idx];
        l1 += x * gw[384 + idx];
        l2 += x * gw[768 + idx];
    }
    l0 = wsum(l0) + gb[0];
    l1 = wsum(l1) + gb[1];
    l2 = wsum(l2) + gb[2];
    const float mx = fmaxf(l0, fmaxf(l1, l2));
    const float e0 = expf(l0 - mx), e1 = expf(l1 - mx), e2 = expf(l2 - mx);
    const float inv = 1.0f / (e0 + e1 + e2);
    const float w0 = e0 * inv, w1 = e1 * inv, w2 = e2 * inv;
#pragma unroll
    for (int j = 0; j < 4; ++j) {
        const int d = lane + 32 * j;
        out[(long)b * 128 + d] = w0 * xr[d] + w1 * xr[128 + d] + w2 * xr[256 + d];
    }
}

// ---------------------------------------------------------------------------

extern "C" void kernel_launch(void* const* d_in, const int* in_sizes, int n_in,
                              void* d_out, int out_size)
{
    const float* x_spatial   = (const float*)d_in[0];
    const float* x_gradient  = (const float*)d_in[1];
    const float* x_frequency = (const float*)d_in[2];
    const float* w_spatial   = (const float*)d_in[3];
    const float* w_gf        = (const float*)d_in[4];
    const float* proj_b      = (const float*)d_in[5];
    const float* proj_ln_g   = (const float*)d_in[6];
    const float* proj_ln_b   = (const float*)d_in[7];
    const float* mod_emb     = (const float*)d_in[8];
    const float* in_w        = (const float*)d_in[9];
    const float* in_b        = (const float*)d_in[10];
    const float* out_w       = (const float*)d_in[11];
    const float* out_b       = (const float*)d_in[12];
    const float* attn_g      = (const float*)d_in[13];
    const float* attn_b      = (const float*)d_in[14];
    const float* w1          = (const float*)d_in[15];
    const float* b1          = (const float*)d_in[16];
    const float* w2          = (const float*)d_in[17];
    const float* b2          = (const float*)d_in[18];
    const float* ffn_g       = (const float*)d_in[19];
    const float* ffn_b       = (const float*)d_in[20];
    const float* gate_w      = (const float*)d_in[21];
    const float* gate_b      = (const float*)d_in[22];
    float* out = (float*)d_out;

    int B = in_sizes[0] / 1280;
    if (B > MAXB) B = MAXB;
    const int gm = (B + 127) / 128;
    const int R  = B * 3;

    k_g_spatial<<<gm, 256>>>(x_spatial, w_spatial, proj_b, B);
    k_g_gf<<<dim3(gm, 2), 256>>>(x_gradient, x_frequency, w_gf, proj_b, B);
    k_ln<<<(R + 7) / 8, 256>>>(0, proj_ln_g, proj_ln_b, mod_emb, R);
    k_g_qkv<<<dim3(gm, 15), 256>>>(in_w, in_b, B);
    k_attn<<<(R + 7) / 8, 256>>>(B);
    k_g_outproj<<<dim3(gm, 3), 256>>>(out_w, out_b, B);
    k_ln<<<(R + 7) / 8, 256>>>(1, attn_g, attn_b, nullptr, R);
    k_g_ffn1<<<dim3(gm, 6), 256>>>(w1, b1, B);
    k_g_ffn2<<<dim3(gm, 3), 256>>>(w2, b2, B);
    k_ln<<<(R + 7) / 8, 256>>>(2, ffn_g, ffn_b, nullptr, R);
    k_gate<<<(B + 7) / 8, 256>>>(gate_w, gate_b, out, B);
}

// round 3
// speedup vs baseline: 1.6207x; 1.0759x over previous
#include <cuda_runtime.h>
#include <math.h>

// ---------------------------------------------------------------------------
// CMAF fused block, round 3: tf32 mma.sync GEMMs with
//   - 64x64 warp tiles (4 warps, CTA 128x128) -> 1.0 LDS/MMA
//   - 20-word smem row pad -> conflict-free fragment loads
//   - cp.async double-buffered staging (raw fp32), cvt.rna at fragment load
// ---------------------------------------------------------------------------

#define MAXB 65536

__device__ __align__(16) float g_P [MAXB * 3 * 128];
__device__ __align__(16) float g_q [MAXB * 3 * 128];
__device__ __align__(16) float g_k [MAXB * 6 * 128];
__device__ __align__(16) float g_v [MAXB * 6 * 128];
__device__ __align__(16) float g_o [MAXB * 3 * 128];
__device__ __align__(16) float g_x1[MAXB * 3 * 128];
__device__ __align__(16) float g_h [MAXB * 3 * 256];
__device__ __align__(16) float g_x2[MAXB * 3 * 128];

__constant__ int c_kv[3][2] = {{1, 2}, {0, 2}, {0, 1}};

__device__ __forceinline__ float wsum(float v) {
#pragma unroll
    for (int o = 16; o; o >>= 1) v += __shfl_xor_sync(0xffffffffu, v, o);
    return v;
}

__device__ __forceinline__ unsigned f2tf(float f) {
    unsigned u;
    asm("cvt.rna.tf32.f32 %0, %1;" : "=r"(u) : "f"(f));
    return u;
}

__device__ __forceinline__ void mma8(float c[4], const unsigned a[4], const unsigned b[2]) {
    asm volatile(
        "mma.sync.aligned.m16n8k8.row.col.f32.tf32.tf32.f32 "
        "{%0,%1,%2,%3}, {%4,%5,%6,%7}, {%8,%9}, {%0,%1,%2,%3};\n"
        : "+f"(c[0]), "+f"(c[1]), "+f"(c[2]), "+f"(c[3])
        : "r"(a[0]), "r"(a[1]), "r"(a[2]), "r"(a[3]), "r"(b[0]), "r"(b[1]));
}

__device__ __forceinline__ void cp16(unsigned smem_dst, const void* gsrc) {
    asm volatile("cp.async.cg.shared.global [%0], [%1], 16;\n"
                 :: "r"(smem_dst), "l"(gsrc));
}
__device__ __forceinline__ void cp_commit() {
    asm volatile("cp.async.commit_group;\n");
}
template <int N>
__device__ __forceinline__ void cp_wait() {
    asm volatile("cp.async.wait_group %0;\n" :: "n"(N));
}

// ---------------------------------------------------------------------------
// GEMM: C[m0:m0+128, 0:128] = A[*, :K] @ W[128, :K]^T  (+bias, opt gelu)
// 128 threads = 4 warps, warp grid 2x2, warp tile 64x64 (mt=4, nt=8).
// ---------------------------------------------------------------------------
template <int EPI>  // 0 = bias, 1 = bias + exact gelu
__device__ __forceinline__ void mma_gemm(
    const float* __restrict__ A, int lda,
    const float* __restrict__ W, int K,
    const float* __restrict__ bias,
    float* __restrict__ out, int ostride,
    int m0, int M)
{
    __shared__ float As[2][128][20];
    __shared__ float Ws[2][128][20];

    const int tid = threadIdx.x;

    // staging: thread <-> one row of each operand, 4 x 16B per tile
    const float* Aptr = A + (long)min(m0 + tid, M - 1) * lda;
    const float* Wptr = W + (long)tid * K;
    const unsigned sA0 = (unsigned)__cvta_generic_to_shared(&As[0][tid][0]);
    const unsigned sA1 = (unsigned)__cvta_generic_to_shared(&As[1][tid][0]);
    const unsigned sW0 = (unsigned)__cvta_generic_to_shared(&Ws[0][tid][0]);
    const unsigned sW1 = (unsigned)__cvta_generic_to_shared(&Ws[1][tid][0]);

    const int wid = tid >> 5, lane = tid & 31;
    const int wm = (wid & 1) * 64;
    const int wn = (wid >> 1) * 64;
    const int g  = lane >> 2, t4 = lane & 3;

    float acc[4][8][4] = {};

    const int ntiles = K >> 4;

    // prologue: tile 0
#pragma unroll
    for (int c = 0; c < 4; ++c) {
        cp16(sA0 + c * 16, Aptr + c * 4);
        cp16(sW0 + c * 16, Wptr + c * 4);
    }
    cp_commit();

    for (int t = 0; t < ntiles; ++t) {
        const int cur = t & 1;
        if (t + 1 < ntiles) {
            const int k0 = (t + 1) << 4;
            const unsigned dA = (cur ? sA0 : sA1);
            const unsigned dW = (cur ? sW0 : sW1);
#pragma unroll
            for (int c = 0; c < 4; ++c) {
                cp16(dA + c * 16, Aptr + k0 + c * 4);
                cp16(dW + c * 16, Wptr + k0 + c * 4);
            }
            cp_commit();
            cp_wait<1>();
        } else {
            cp_wait<0>();
        }
        __syncthreads();

#pragma unroll
        for (int ks = 0; ks < 16; ks += 8) {
            unsigned af[4][4];
#pragma unroll
            for (int mt = 0; mt < 4; ++mt) {
                const int r = wm + mt * 16 + g;
                af[mt][0] = f2tf(As[cur][r][ks + t4]);
                af[mt][1] = f2tf(As[cur][r + 8][ks + t4]);
                af[mt][2] = f2tf(As[cur][r][ks + t4 + 4]);
                af[mt][3] = f2tf(As[cur][r + 8][ks + t4 + 4]);
            }
            unsigned bf[8][2];
#pragma unroll
            for (int nt = 0; nt < 8; ++nt) {
                const int n = wn + nt * 8 + g;
                bf[nt][0] = f2tf(Ws[cur][n][ks + t4]);
                bf[nt][1] = f2tf(Ws[cur][n][ks + t4 + 4]);
            }
#pragma unroll
            for (int mt = 0; mt < 4; ++mt)
#pragma unroll
                for (int nt = 0; nt < 8; ++nt)
                    mma8(acc[mt][nt], af[mt], bf[nt]);
        }
        __syncthreads();
    }

    // ---- epilogue: bias (+gelu) ----
    float bcol[8][2];
#pragma unroll
    for (int nt = 0; nt < 8; ++nt) {
        const int col = wn + nt * 8 + t4 * 2;
        bcol[nt][0] = bias[col];
        bcol[nt][1] = bias[col + 1];
    }
#pragma unroll
    for (int mt = 0; mt < 4; ++mt)
#pragma unroll
        for (int half = 0; half < 2; ++half) {
            const int r = m0 + wm + mt * 16 + half * 8 + g;
            if (r < M) {
                float* orow = out + (long)r * ostride;
#pragma unroll
                for (int nt = 0; nt < 8; ++nt) {
                    const int col = wn + nt * 8 + t4 * 2;
                    float c0 = acc[mt][nt][half * 2 + 0] + bcol[nt][0];
                    float c1 = acc[mt][nt][half * 2 + 1] + bcol[nt][1];
                    if (EPI == 1) {
                        c0 = c0 * 0.5f * (1.0f + erff(c0 * 0.70710678118654752f));
                        c1 = c1 * 0.5f * (1.0f + erff(c1 * 0.70710678118654752f));
                    }
                    *(float2*)(orow + col) = make_float2(c0, c1);
                }
            }
        }
}

// ---------------- GEMM wrappers ----------------

__global__ __launch_bounds__(128, 2) void k_g_spatial(
    const float* __restrict__ X, const float* __restrict__ W,
    const float* __restrict__ pb, int M)
{
    mma_gemm<0>(X, 1280, W, 1280, pb, g_P, 384, blockIdx.x * 128, M);
}

__global__ __launch_bounds__(128, 2) void k_g_gf(
    const float* __restrict__ Xg, const float* __restrict__ Xf,
    const float* __restrict__ Wgf, const float* __restrict__ pb, int M)
{
    const int s = blockIdx.y;     // 0->grad(n=1), 1->freq(n=2)
    const int n = s + 1;
    mma_gemm<0>(s ? Xf : Xg, 128, Wgf + s * 128 * 128, 128,
                pb + n * 128, g_P + n * 128, 384, blockIdx.x * 128, M);
}

__global__ __launch_bounds__(128, 2) void k_g_qkv(
    const float* __restrict__ Wi, const float* __restrict__ Bi, int M)
{
    const int j = blockIdx.y;   // 0..14
    const int n = j / 5, t = j % 5;
    int src, wpart, outoff, ostride;
    float* outbuf;
    if (t == 0)      { src = n;             wpart = 0; outbuf = g_q; outoff = n * 128;               ostride = 384; }
    else if (t <= 2) { const int s = t - 1; src = c_kv[n][s]; wpart = 1; outbuf = g_k; outoff = (n * 2 + s) * 128; ostride = 768; }
    else             { const int s = t - 3; src = c_kv[n][s]; wpart = 2; outbuf = g_v; outoff = (n * 2 + s) * 128; ostride = 768; }
    mma_gemm<0>(g_P + src * 128, 384,
                Wi + n * 384 * 128 + wpart * 128 * 128, 128,
                Bi + n * 384 + wpart * 128,
                outbuf + outoff, ostride, blockIdx.x * 128, M);
}

__global__ __launch_bounds__(128, 2) void k_g_outproj(
    const float* __restrict__ Wo, const float* __restrict__ bo, int M)
{
    const int n = blockIdx.y;
    mma_gemm<0>(g_o + n * 128, 384, Wo + n * 128 * 128, 128,
                bo + n * 128, g_x1 + n * 128, 384, blockIdx.x * 128, M);
}

__global__ __launch_bounds__(128, 2) void k_g_ffn1(
    const float* __restrict__ W1, const float* __restrict__ B1, int M)
{
    const int j = blockIdx.y;    // 0..5
    const int n = j >> 1, tl = j & 1;
    mma_gemm<1>(g_x1 + n * 128, 384,
                W1 + n * 256 * 128 + tl * 128 * 128, 128,
                B1 + n * 256 + tl * 128,
                g_h + n * 256 + tl * 128, 768, blockIdx.x * 128, M);
}

__global__ __launch_bounds__(128, 2) void k_g_ffn2(
    const float* __restrict__ W2, const float* __restrict__ B2, int M)
{
    const int n = blockIdx.y;
    mma_gemm<0>(g_h + n * 256, 768, W2 + n * 128 * 256, 256,
                B2 + n * 128, g_x2 + n * 128, 384, blockIdx.x * 128, M);
}

// ---------------- LayerNorm passes ----------------
// mode 0: g_P  = LN(g_P)*g+b + mod      (proj)
// mode 1: g_x1 = LN(g_x1 + g_P)*g+b     (post-attn)
// mode 2: g_x2 = LN(g_x2 + g_x1)*g+b    (post-ffn)
__global__ __launch_bounds__(256) void k_ln(
    int mode,
    const float* __restrict__ gamma, const float* __restrict__ beta,
    const float* __restrict__ addv, int R)
{
    const int row = blockIdx.x * 8 + (threadIdx.x >> 5);
    if (row >= R) return;
    const int lane = threadIdx.x & 31;
    const int n = row % 3;

    float* io = (mode == 0) ? g_P : (mode == 1 ? g_x1 : g_x2);
    const float* resid = (mode == 0) ? nullptr : (mode == 1 ? g_P : g_x1);

    const long off = (long)row * 128 + lane * 4;
    float4 v = *(const float4*)(io + off);
    if (resid) {
        float4 r4 = *(const float4*)(resid + off);
        v.x += r4.x; v.y += r4.y; v.z += r4.z; v.w += r4.w;
    }
    float s  = v.x + v.y + v.z + v.w;
    float s2 = v.x * v.x + v.y * v.y + v.z * v.z + v.w * v.w;
    s  = wsum(s);
    s2 = wsum(s2);
    const float mean = s * 0.0078125f;
    const float var  = s2 * 0.0078125f - mean * mean;
    const float rs   = rsqrtf(var + 1e-5f);

    const int pidx = n * 128 + lane * 4;
    const float4 g4 = *(const float4*)(gamma + pidx);
    const float4 b4 = *(const float4*)(beta + pidx);
    float4 m4 = make_float4(0.f, 0.f, 0.f, 0.f);
    if (addv) m4 = *(const float4*)(addv + pidx);

    float4 o;
    o.x = (v.x - mean) * rs * g4.x + b4.x + m4.x;
    o.y = (v.y - mean) * rs * g4.y + b4.y + m4.y;
    o.z = (v.z - mean) * rs * g4.z + b4.z + m4.z;
    o.w = (v.w - mean) * rs * g4.w + b4.w + m4.w;
    *(float4*)(io + off) = o;
}

// ---------------- Attention + gate ----------------

__global__ __launch_bounds__(256) void k_attn(int M)
{
    const int rid = blockIdx.x * 8 + (threadIdx.x >> 5);
    if (rid >= M * 3) return;
    const int lane = threadIdx.x & 31;
    const long base = (long)rid * 128;
    const float* qr = g_q + base;
    const float* kr = g_k + base * 2;
    const float* vr = g_v + base * 2;
    float* orow     = g_o + base;
    const float scale = 0.17677669529663687f;  // 1/sqrt(32)
#pragma unroll
    for (int h = 0; h < 4; ++h) {
        const int d = h * 32 + lane;
        const float qv = qr[d];
        float s0 = qv * kr[d];
        float s1 = qv * kr[128 + d];
        s0 = wsum(s0) * scale;
        s1 = wsum(s1) * scale;
        const float mx = fmaxf(s0, s1);
        const float e0 = expf(s0 - mx), e1 = expf(s1 - mx);
        const float inv = 1.0f / (e0 + e1);
        orow[d] = (e0 * inv) * vr[d] + (e1 * inv) * vr[128 + d];
    }
}

__global__ __launch_bounds__(256) void k_gate(
    const float* __restrict__ gw, const float* __restrict__ gb,
    float* __restrict__ out, int M)
{
    const int b = blockIdx.x * 8 + (threadIdx.x >> 5);
    if (b >= M) return;
    const int lane = threadIdx.x & 31;
    const float* xr = g_x2 + (long)b * 384;
    float l0 = 0.f, l1 = 0.f, l2 = 0.f;
#pragma unroll
    for (int j = 0; j < 12; ++j) {
        const int idx = lane + 32 * j;
        const float x = xr[idx];
        l0 += x * gw[idx];
        l1 += x * gw[384 + idx];
        l2 += x * gw[768 + idx];
    }
    l0 = wsum(l0) + gb[0];
    l1 = wsum(l1) + gb[1];
    l2 = wsum(l2) + gb[2];
    const float mx = fmaxf(l0, fmaxf(l1, l2));
    const float e0 = expf(l0 - mx), e1 = expf(l1 - mx), e2 = expf(l2 - mx);
    const float inv = 1.0f / (e0 + e1 + e2);
    const float w0 = e0 * inv, w1 = e1 * inv, w2 = e2 * inv;
#pragma unroll
    for (int j = 0; j < 4; ++j) {
        const int d = lane + 32 * j;
        out[(long)b * 128 + d] = w0 * xr[d] + w1 * xr[128 + d] + w2 * xr[256 + d];
    }
}

// ---------------------------------------------------------------------------

extern "C" void kernel_launch(void* const* d_in, const int* in_sizes, int n_in,
                              void* d_out, int out_size)
{
    const float* x_spatial   = (const float*)d_in[0];
    const float* x_gradient  = (const float*)d_in[1];
    const float* x_frequency = (const float*)d_in[2];
    const float* w_spatial   = (const float*)d_in[3];
    const float* w_gf        = (const float*)d_in[4];
    const float* proj_b      = (const float*)d_in[5];
    const float* proj_ln_g   = (const float*)d_in[6];
    const float* proj_ln_b   = (const float*)d_in[7];
    const float* mod_emb     = (const float*)d_in[8];
    const float* in_w        = (const float*)d_in[9];
    const float* in_b        = (const float*)d_in[10];
    const float* out_w       = (const float*)d_in[11];
    const float* out_b       = (const float*)d_in[12];
    const float* attn_g      = (const float*)d_in[13];
    const float* attn_b      = (const float*)d_in[14];
    const float* w1          = (const float*)d_in[15];
    const float* b1          = (const float*)d_in[16];
    const float* w2          = (const float*)d_in[17];
    const float* b2          = (const float*)d_in[18];
    const float* ffn_g       = (const float*)d_in[19];
    const float* ffn_b       = (const float*)d_in[20];
    const float* gate_w      = (const float*)d_in[21];
    const float* gate_b      = (const float*)d_in[22];
    float* out = (float*)d_out;

    int B = in_sizes[0] / 1280;
    if (B > MAXB) B = MAXB;
    const int gm = (B + 127) / 128;
    const int R  = B * 3;

    k_g_spatial<<<gm, 128>>>(x_spatial, w_spatial, proj_b, B);
    k_g_gf<<<dim3(gm, 2), 128>>>(x_gradient, x_frequency, w_gf, proj_b, B);
    k_ln<<<(R + 7) / 8, 256>>>(0, proj_ln_g, proj_ln_b, mod_emb, R);
    k_g_qkv<<<dim3(gm, 15), 128>>>(in_w, in_b, B);
    k_attn<<<(R + 7) / 8, 256>>>(B);
    k_g_outproj<<<dim3(gm, 3), 128>>>(out_w, out_b, B);
    k_ln<<<(R + 7) / 8, 256>>>(1, attn_g, attn_b, nullptr, R);
    k_g_ffn1<<<dim3(gm, 6), 128>>>(w1, b1, B);
    k_g_ffn2<<<dim3(gm, 3), 128>>>(w2, b2, B);
    k_ln<<<(R + 7) / 8, 256>>>(2, ffn_g, ffn_b, nullptr, R);
    k_gate<<<(B + 7) / 8, 256>>>(gate_w, gate_b, out, B);
}

// round 4
// speedup vs baseline: 1.8606x; 1.1481x over previous
#include <cuda_runtime.h>
#include <math.h>

// ---------------------------------------------------------------------------
// CMAF fused block, round 4:
//   - GEMM: 256 thr / 8 warps, warp tile 64x32, 3-stage cp.async pipeline,
//     dynamic smem (61.4KB), 20-word pad (conflict-free frag loads)
//   - QKV fused per source stream (5 output blocks reuse A via L2)
//   - FFN1 fused (2 output blocks per stream)
//   - attn vectorized float4 + octet shuffle reduce
// ---------------------------------------------------------------------------

#define MAXB 65536

__device__ __align__(16) float g_P [MAXB * 3 * 128];
__device__ __align__(16) float g_q [MAXB * 3 * 128];
__device__ __align__(16) float g_k [MAXB * 6 * 128];
__device__ __align__(16) float g_v [MAXB * 6 * 128];
__device__ __align__(16) float g_o [MAXB * 3 * 128];
__device__ __align__(16) float g_x1[MAXB * 3 * 128];
__device__ __align__(16) float g_h [MAXB * 3 * 256];
__device__ __align__(16) float g_x2[MAXB * 3 * 128];

// QKV jobs per source stream s: {w_off, b_off, buf_id, out_off}
// buf_id: 0=q(stride 384), 1=k(stride 768), 2=v(stride 768)
__constant__ int qkv_jobs[3][5][4] = {
    { {     0,    0, 0,   0}, { 65536,  512, 1, 256}, { 81920,  640, 2, 256},
      {114688,  896, 1, 512}, {131072, 1024, 2, 512} },
    { { 49152,  384, 0, 128}, { 16384,  128, 1,   0}, { 32768,  256, 2,   0},
      {114688,  896, 1, 640}, {131072, 1024, 2, 640} },
    { { 98304,  768, 0, 256}, { 16384,  128, 1, 128}, { 32768,  256, 2, 128},
      { 65536,  512, 1, 384}, { 81920,  640, 2, 384} },
};

#define GSMEM (3 * 2 * 128 * 20 * 4)   // 61440 bytes

__device__ __forceinline__ float wsum(float v) {
#pragma unroll
    for (int o = 16; o; o >>= 1) v += __shfl_xor_sync(0xffffffffu, v, o);
    return v;
}

__device__ __forceinline__ unsigned f2tf(float f) {
    unsigned u;
    asm("cvt.rna.tf32.f32 %0, %1;" : "=r"(u) : "f"(f));
    return u;
}

__device__ __forceinline__ void mma8(float c[4], const unsigned a[4], const unsigned b[2]) {
    asm volatile(
        "mma.sync.aligned.m16n8k8.row.col.f32.tf32.tf32.f32 "
        "{%0,%1,%2,%3}, {%4,%5,%6,%7}, {%8,%9}, {%0,%1,%2,%3};\n"
        : "+f"(c[0]), "+f"(c[1]), "+f"(c[2]), "+f"(c[3])
        : "r"(a[0]), "r"(a[1]), "r"(a[2]), "r"(a[3]), "r"(b[0]), "r"(b[1]));
}

__device__ __forceinline__ void cp16(unsigned smem_dst, const void* gsrc) {
    asm volatile("cp.async.cg.shared.global [%0], [%1], 16;\n"
                 :: "r"(smem_dst), "l"(gsrc));
}
__device__ __forceinline__ void cp_commit() {
    asm volatile("cp.async.commit_group;\n");
}
template <int N>
__device__ __forceinline__ void cp_wait() {
    asm volatile("cp.async.wait_group %0;\n" :: "n"(N));
}

// smem layout helpers (dynamic): A stages then W stages, rows padded to 20
#define AS_IDX(s, r, c) (((s) * 128 + (r)) * 20 + (c))
#define WS_IDX(s, r, c) (3 * 128 * 20 + ((s) * 128 + (r)) * 20 + (c))

// ---------------------------------------------------------------------------
// C[m0:m0+128, 0:128] = A[*, :K] @ W[128, :K]^T  (+bias, opt gelu)
// 256 threads = 8 warps, warp grid 2(m) x 4(n), warp tile 64x32.
// 3-stage cp.async pipeline, BK=16. Requires K % 16 == 0, K >= 32.
// ---------------------------------------------------------------------------
template <int EPI>  // 0 = bias, 1 = bias + exact gelu
__device__ __forceinline__ void mma_gemm(
    const float* __restrict__ A, int lda,
    const float* __restrict__ W, int K,
    const float* __restrict__ bias,
    float* __restrict__ out, int ostride,
    int m0, int M)
{
    extern __shared__ float smem[];

    __syncthreads();   // guard smem reuse across consecutive calls

    const int tid   = threadIdx.x;
    const int ldRow = tid >> 1;          // 0..127
    const int ldCol = (tid & 1) * 8;     // 0 or 8

    const float* Aptr = A + (long)min(m0 + ldRow, M - 1) * lda + ldCol;
    const float* Wptr = W + (long)ldRow * K + ldCol;

    unsigned sa[3], sw[3];
#pragma unroll
    for (int s = 0; s < 3; ++s) {
        sa[s] = (unsigned)__cvta_generic_to_shared(&smem[AS_IDX(s, ldRow, ldCol)]);
        sw[s] = (unsigned)__cvta_generic_to_shared(&smem[WS_IDX(s, ldRow, ldCol)]);
    }

    const int wid = tid >> 5, lane = tid & 31;
    const int wm = (wid & 1) * 64;
    const int wn = (wid >> 1) * 32;
    const int g  = lane >> 2, t4 = lane & 3;

    float acc[4][4][4] = {};

    const int ntiles = K >> 4;

    // prologue: stages 0,1
#pragma unroll
    for (int p = 0; p < 2; ++p) {
        const int k0 = p << 4;
        cp16(sa[p],      Aptr + k0);
        cp16(sa[p] + 16, Aptr + k0 + 4);
        cp16(sw[p],      Wptr + k0);
        cp16(sw[p] + 16, Wptr + k0 + 4);
        cp_commit();
    }

    int cur = 0;
    for (int t = 0; t < ntiles; ++t) {
        if (t + 2 < ntiles) cp_wait<1>(); else cp_wait<0>();
        __syncthreads();

        const int pf = t + 2;
        if (pf < ntiles) {
            const int buf = (cur + 2 >= 3) ? cur - 1 : cur + 2;
            const int k0 = pf << 4;
            cp16(sa[buf],      Aptr + k0);
            cp16(sa[buf] + 16, Aptr + k0 + 4);
            cp16(sw[buf],      Wptr + k0);
            cp16(sw[buf] + 16, Wptr + k0 + 4);
            cp_commit();
        }

#pragma unroll
        for (int ks = 0; ks < 16; ks += 8) {
            unsigned af[4][4];
#pragma unroll
            for (int mt = 0; mt < 4; ++mt) {
                const int r = wm + mt * 16 + g;
                af[mt][0] = f2tf(smem[AS_IDX(cur, r,     ks + t4)]);
                af[mt][1] = f2tf(smem[AS_IDX(cur, r + 8, ks + t4)]);
                af[mt][2] = f2tf(smem[AS_IDX(cur, r,     ks + t4 + 4)]);
                af[mt][3] = f2tf(smem[AS_IDX(cur, r + 8, ks + t4 + 4)]);
            }
            unsigned bf[4][2];
#pragma unroll
            for (int nt = 0; nt < 4; ++nt) {
                const int n = wn + nt * 8 + g;
                bf[nt][0] = f2tf(smem[WS_IDX(cur, n, ks + t4)]);
                bf[nt][1] = f2tf(smem[WS_IDX(cur, n, ks + t4 + 4)]);
            }
#pragma unroll
            for (int mt = 0; mt < 4; ++mt)
#pragma unroll
                for (int nt = 0; nt < 4; ++nt)
                    mma8(acc[mt][nt], af[mt], bf[nt]);
        }
        cur = (cur + 1 >= 3) ? 0 : cur + 1;
    }

    // ---- epilogue: bias (+gelu) ----
    float bcol[4][2];
#pragma unroll
    for (int nt = 0; nt < 4; ++nt) {
        const int col = wn + nt * 8 + t4 * 2;
        bcol[nt][0] = bias[col];
        bcol[nt][1] = bias[col + 1];
    }
#pragma unroll
    for (int mt = 0; mt < 4; ++mt)
#pragma unroll
        for (int half = 0; half < 2; ++half) {
            const int r = m0 + wm + mt * 16 + half * 8 + g;
            if (r < M) {
                float* orow = out + (long)r * ostride;
#pragma unroll
                for (int nt = 0; nt < 4; ++nt) {
                    const int col = wn + nt * 8 + t4 * 2;
                    float c0 = acc[mt][nt][half * 2 + 0] + bcol[nt][0];
                    float c1 = acc[mt][nt][half * 2 + 1] + bcol[nt][1];
                    if (EPI == 1) {
                        c0 = c0 * 0.5f * (1.0f + erff(c0 * 0.70710678118654752f));
                        c1 = c1 * 0.5f * (1.0f + erff(c1 * 0.70710678118654752f));
                    }
                    *(float2*)(orow + col) = make_float2(c0, c1);
                }
            }
        }
}

// ---------------- GEMM wrappers ----------------

__global__ __launch_bounds__(256, 2) void k_g_spatial(
    const float* __restrict__ X, const float* __restrict__ W,
    const float* __restrict__ pb, int M)
{
    mma_gemm<0>(X, 1280, W, 1280, pb, g_P, 384, blockIdx.x * 128, M);
}

__global__ __launch_bounds__(256, 2) void k_g_gf(
    const float* __restrict__ Xg, const float* __restrict__ Xf,
    const float* __restrict__ Wgf, const float* __restrict__ pb, int M)
{
    const int s = blockIdx.y;     // 0->grad(n=1), 1->freq(n=2)
    const int n = s + 1;
    mma_gemm<0>(s ? Xf : Xg, 128, Wgf + s * 128 * 128, 128,
                pb + n * 128, g_P + n * 128, 384, blockIdx.x * 128, M);
}

__global__ __launch_bounds__(256, 2) void k_g_qkv(
    const float* __restrict__ Wi, const float* __restrict__ Bi, int M)
{
    const int s  = blockIdx.y;          // source stream
    const int m0 = blockIdx.x * 128;
    const float* A = g_P + s * 128;
    float* bufs[3] = {g_q, g_k, g_v};
#pragma unroll 1
    for (int j = 0; j < 5; ++j) {
        const int woff = qkv_jobs[s][j][0];
        const int boff = qkv_jobs[s][j][1];
        const int bid  = qkv_jobs[s][j][2];
        const int ooff = qkv_jobs[s][j][3];
        mma_gemm<0>(A, 384, Wi + woff, 128, Bi + boff,
                    bufs[bid] + ooff, bid == 0 ? 384 : 768, m0, M);
    }
}

__global__ __launch_bounds__(256, 2) void k_g_outproj(
    const float* __restrict__ Wo, const float* __restrict__ bo, int M)
{
    const int n = blockIdx.y;
    mma_gemm<0>(g_o + n * 128, 384, Wo + n * 128 * 128, 128,
                bo + n * 128, g_x1 + n * 128, 384, blockIdx.x * 128, M);
}

__global__ __launch_bounds__(256, 2) void k_g_ffn1(
    const float* __restrict__ W1, const float* __restrict__ B1, int M)
{
    const int n  = blockIdx.y;
    const int m0 = blockIdx.x * 128;
#pragma unroll 1
    for (int tl = 0; tl < 2; ++tl)
        mma_gemm<1>(g_x1 + n * 128, 384,
                    W1 + n * 256 * 128 + tl * 128 * 128, 128,
                    B1 + n * 256 + tl * 128,
                    g_h + n * 256 + tl * 128, 768, m0, M);
}

__global__ __launch_bounds__(256, 2) void k_g_ffn2(
    const float* __restrict__ W2, const float* __restrict__ B2, int M)
{
    const int n = blockIdx.y;
    mma_gemm<0>(g_h + n * 256, 768, W2 + n * 128 * 256, 256,
                B2 + n * 128, g_x2 + n * 128, 384, blockIdx.x * 128, M);
}

// ---------------- LayerNorm passes ----------------
__global__ __launch_bounds__(256) void k_ln(
    int mode,
    const float* __restrict__ gamma, const float* __restrict__ beta,
    const float* __restrict__ addv, int R)
{
    const int row = blockIdx.x * 8 + (threadIdx.x >> 5);
    if (row >= R) return;
    const int lane = threadIdx.x & 31;
    const int n = row % 3;

    float* io = (mode == 0) ? g_P : (mode == 1 ? g_x1 : g_x2);
    const float* resid = (mode == 0) ? nullptr : (mode == 1 ? g_P : g_x1);

    const long off = (long)row * 128 + lane * 4;
    float4 v = *(const float4*)(io + off);
    if (resid) {
        float4 r4 = *(const float4*)(resid + off);
        v.x += r4.x; v.y += r4.y; v.z += r4.z; v.w += r4.w;
    }
    float s  = v.x + v.y + v.z + v.w;
    float s2 = v.x * v.x + v.y * v.y + v.z * v.z + v.w * v.w;
    s  = wsum(s);
    s2 = wsum(s2);
    const float mean = s * 0.0078125f;
    const float var  = s2 * 0.0078125f - mean * mean;
    const float rs   = rsqrtf(var + 1e-5f);

    const int pidx = n * 128 + lane * 4;
    const float4 g4 = *(const float4*)(gamma + pidx);
    const float4 b4 = *(const float4*)(beta + pidx);
    float4 m4 = make_float4(0.f, 0.f, 0.f, 0.f);
    if (addv) m4 = *(const float4*)(addv + pidx);

    float4 o;
    o.x = (v.x - mean) * rs * g4.x + b4.x + m4.x;
    o.y = (v.y - mean) * rs * g4.y + b4.y + m4.y;
    o.z = (v.z - mean) * rs * g4.z + b4.z + m4.z;
    o.w = (v.w - mean) * rs * g4.w + b4.w + m4.w;
    *(float4*)(io + off) = o;
}

// ---------------- Attention (float4 + octet reduce) ----------------

__global__ __launch_bounds__(256) void k_attn(int M)
{
    const int rid = blockIdx.x * 8 + (threadIdx.x >> 5);
    if (rid >= M * 3) return;
    const int lane = threadIdx.x & 31;
    const int d4 = lane * 4;                   // head h = lane>>3
    const long qb = (long)rid * 128;
    const long kb = (long)rid * 256;

    const float4 q4  = *(const float4*)(g_q + qb + d4);
    const float4 k04 = *(const float4*)(g_k + kb + d4);
    const float4 k14 = *(const float4*)(g_k + kb + 128 + d4);
    const float4 v04 = *(const float4*)(g_v + kb + d4);
    const float4 v14 = *(const float4*)(g_v + kb + 128 + d4);

    float s0 = q4.x * k04.x + q4.y * k04.y + q4.z * k04.z + q4.w * k04.w;
    float s1 = q4.x * k14.x + q4.y * k14.y + q4.z * k14.z + q4.w * k14.w;
#pragma unroll
    for (int o = 4; o; o >>= 1) {
        s0 += __shfl_xor_sync(0xffffffffu, s0, o);
        s1 += __shfl_xor_sync(0xffffffffu, s1, o);
    }
    const float scale = 0.17677669529663687f;  // 1/sqrt(32)
    s0 *= scale; s1 *= scale;
    const float mx = fmaxf(s0, s1);
    const float e0 = expf(s0 - mx), e1 = expf(s1 - mx);
    const float inv = 1.0f / (e0 + e1);
    const float w0 = e0 * inv, w1 = e1 * inv;

    float4 o4;
    o4.x = w0 * v04.x + w1 * v14.x;
    o4.y = w0 * v04.y + w1 * v14.y;
    o4.z = w0 * v04.z + w1 * v14.z;
    o4.w = w0 * v04.w + w1 * v14.w;
    *(float4*)(g_o + qb + d4) = o4;
}

__global__ __launch_bounds__(256) void k_gate(
    const float* __restrict__ gw, const float* __restrict__ gb,
    float* __restrict__ out, int M)
{
    const int b = blockIdx.x * 8 + (threadIdx.x >> 5);
    if (b >= M) return;
    const int lane = threadIdx.x & 31;
    const float* xr = g_x2 + (long)b * 384;
    float l0 = 0.f, l1 = 0.f, l2 = 0.f;
#pragma unroll
    for (int j = 0; j < 12; ++j) {
        const int idx = lane + 32 * j;
        const float x = xr[idx];
        l0 += x * gw[idx];
        l1 += x * gw[384 + idx];
        l2 += x * gw[768 + idx];
    }
    l0 = wsum(l0) + gb[0];
    l1 = wsum(l1) + gb[1];
    l2 = wsum(l2) + gb[2];
    const float mx = fmaxf(l0, fmaxf(l1, l2));
    const float e0 = expf(l0 - mx), e1 = expf(l1 - mx), e2 = expf(l2 - mx);
    const float inv = 1.0f / (e0 + e1 + e2);
    const float w0 = e0 * inv, w1 = e1 * inv, w2 = e2 * inv;
#pragma unroll
    for (int j = 0; j < 4; ++j) {
        const int d = lane + 32 * j;
        out[(long)b * 128 + d] = w0 * xr[d] + w1 * xr[128 + d] + w2 * xr[256 + d];
    }
}

// ---------------------------------------------------------------------------

extern "C" void kernel_launch(void* const* d_in, const int* in_sizes, int n_in,
                              void* d_out, int out_size)
{
    const float* x_spatial   = (const float*)d_in[0];
    const float* x_gradient  = (const float*)d_in[1];
    const float* x_frequency = (const float*)d_in[2];
    const float* w_spatial   = (const float*)d_in[3];
    const float* w_gf        = (const float*)d_in[4];
    const float* proj_b      = (const float*)d_in[5];
    const float* proj_ln_g   = (const float*)d_in[6];
    const float* proj_ln_b   = (const float*)d_in[7];
    const float* mod_emb     = (const float*)d_in[8];
    const float* in_w        = (const float*)d_in[9];
    const float* in_b        = (const float*)d_in[10];
    const float* out_w       = (const float*)d_in[11];
    const float* out_b       = (const float*)d_in[12];
    const float* attn_g      = (const float*)d_in[13];
    const float* attn_b      = (const float*)d_in[14];
    const float* w1          = (const float*)d_in[15];
    const float* b1          = (const float*)d_in[16];
    const float* w2          = (const float*)d_in[17];
    const float* b2          = (const float*)d_in[18];
    const float* ffn_g       = (const float*)d_in[19];
    const float* ffn_b       = (const float*)d_in[20];
    const float* gate_w      = (const float*)d_in[21];
    const float* gate_b      = (const float*)d_in[22];
    float* out = (float*)d_out;

    static int smem_set = 0;
    if (!smem_set) {
        cudaFuncSetAttribute(k_g_spatial, cudaFuncAttributeMaxDynamicSharedMemorySize, GSMEM);
        cudaFuncSetAttribute(k_g_gf,      cudaFuncAttributeMaxDynamicSharedMemorySize, GSMEM);
        cudaFuncSetAttribute(k_g_qkv,     cudaFuncAttributeMaxDynamicSharedMemorySize, GSMEM);
        cudaFuncSetAttribute(k_g_outproj, cudaFuncAttributeMaxDynamicSharedMemorySize, GSMEM);
        cudaFuncSetAttribute(k_g_ffn1,    cudaFuncAttributeMaxDynamicSharedMemorySize, GSMEM);
        cudaFuncSetAttribute(k_g_ffn2,    cudaFuncAttributeMaxDynamicSharedMemorySize, GSMEM);
        smem_set = 1;
    }

    int B = in_sizes[0] / 1280;
    if (B > MAXB) B = MAXB;
    const int gm = (B + 127) / 128;
    const int R  = B * 3;

    k_g_spatial<<<gm, 256, GSMEM>>>(x_spatial, w_spatial, proj_b, B);
    k_g_gf<<<dim3(gm, 2), 256, GSMEM>>>(x_gradient, x_frequency, w_gf, proj_b, B);
    k_ln<<<(R + 7) / 8, 256>>>(0, proj_ln_g, proj_ln_b, mod_emb, R);
    k_g_qkv<<<dim3(gm, 3), 256, GSMEM>>>(in_w, in_b, B);
    k_attn<<<(R + 7) / 8, 256>>>(B);
    k_g_outproj<<<dim3(gm, 3), 256, GSMEM>>>(out_w, out_b, B);
    k_ln<<<(R + 7) / 8, 256>>>(1, attn_g, attn_b, nullptr, R);
    k_g_ffn1<<<dim3(gm, 3), 256, GSMEM>>>(w1, b1, B);
    k_g_ffn2<<<dim3(gm, 3), 256, GSMEM>>>(w2, b2, B);
    k_ln<<<(R + 7) / 8, 256>>>(2, ffn_g, ffn_b, nullptr, R);
    k_gate<<<(B + 7) / 8, 256>>>(gate_w, gate_b, out, B);
}